// round 15
// baseline (speedup 1.0000x reference)
#include <cuda_runtime.h>

// ---------------------------------------------------------------------------
// AdaptiveUnivariateFunction — fused persistent kernel (round 15).
//   xn = (x - min)/(max - min + 1e-6) in [0,1)
//   out = cp[idx] + t*(cp[idx+1]-cp[idx]),  idx=clamp(floor(xn*31),0,30)
//
// vs round 14: WARP-AUTONOMOUS dynamic claiming. Each warp claims 16KB
// chunks (lane-0 atomicAdd + shfl broadcast) — no __syncthreads in the
// dynamic loops, no inter-warp coupling, claim latency hidden under the
// chunk body. This recovers the overlap the (racy) R9 loop had, legally.
//
// Validated knobs kept: tail 96MB natural LRU, tail-first phase 2, .cs
// loads/stores, per-thread static tail loops, ping-pong barrier state.
// ---------------------------------------------------------------------------

#define NPART 1184               // 148 SMs x 8 blocks -> exactly one wave
#define NTHREADS 256
#define WCHUNK_ITERS 32          // warp iterations per claimed chunk
#define WCHUNK_V4 (WCHUNK_ITERS * 32)      // 1024 float4 = 16 KB per claim
#define TAIL_V4 6291456          // 96 MB / 16 B static tail (L2-fresh)

// ping-pong state; slot = epoch & 1
__device__ unsigned int g_mm[2][2] = {{0xFFFFFFFFu, 0u}, {0xFFFFFFFFu, 0u}};
__device__ float2 g_sb[2];                 // published (S, B)
__device__ unsigned int g_ctr1[2];         // phase-1 chunk counter
__device__ unsigned int g_ctr2[2];         // phase-2 chunk counter
__device__ unsigned int g_count;           // barrier arrivals
__device__ unsigned int g_release;         // barrier epoch (monotone)

__device__ __forceinline__ unsigned int ld_acq(const unsigned int* p) {
    unsigned int v;
    asm volatile("ld.global.acquire.gpu.u32 %0, [%1];" : "=r"(v) : "l"(p));
    return v;
}
__device__ __forceinline__ unsigned int flipf(float f) {
    unsigned int u = __float_as_uint(f);
    return u ^ ((unsigned int)(-(int)(u >> 31)) | 0x80000000u);
}
__device__ __forceinline__ float unflipf(unsigned int u) {
    return __uint_as_float(u ^ (((u >> 31) - 1u) | 0x80000000u));
}

__device__ __forceinline__ float auf_eval(float x, float S, float B,
                                          const float2* __restrict__ tab) {
    float xn31 = fmaf(x, S, B);            // xn * 31
    int idx = (int)xn31;                   // trunc == floor here
    idx = max(0, min(idx, 30));            // boundary rounding value-neutral
    float2 ad = tab[idx];                  // (cp[idx], cp[idx+1]-cp[idx])
    return fmaf(xn31 - (float)idx, ad.y, ad.x);
}

__global__ void __launch_bounds__(NTHREADS, 8)
auf_fused_kernel(const float* __restrict__ xs,
                 const float* __restrict__ cp,
                 float* __restrict__ outs,
                 int n) {
    __shared__ float2 tab[32];
    __shared__ float smin[8], smax[8];
    __shared__ float s_SB[2];

    const int lane = threadIdx.x & 31;
    const int wid  = threadIdx.x >> 5;

    // epoch/slot (thread 0 reads; slot rebroadcast to warp leaders via shfl
    // is unnecessary — each warp leader re-derives it)
    unsigned int epoch0 = 0;
    if (threadIdx.x == 0) epoch0 = ld_acq(&g_release);
    // every warp leader needs slot for its claims: read epoch per-warp
    unsigned int wepoch = 0;
    if (lane == 0) wepoch = ld_acq(&g_release);
    wepoch = __shfl_sync(0xFFFFFFFFu, wepoch, 0);
    const int slot = (int)(wepoch & 1u);

    // spline table: (cp[i], cp[i+1]-cp[i]); slot 31 duplicates 30
    if (threadIdx.x < 32) {
        int i = (threadIdx.x < 31) ? (int)threadIdx.x : 30;
        float c0 = cp[i];
        float c1 = cp[i + 1];
        tab[threadIdx.x] = make_float2(c0, c1 - c0);
    }
    __syncthreads();                       // tab visible to all warps

    const float4* __restrict__ x4 = (const float4*)xs;
    const int nv4 = n >> 2;
    const int tid0 = blockIdx.x * NTHREADS + (int)threadIdx.x;
    const int stride = NPART * NTHREADS;

    // region split: dynamic warp chunks over [0, tail_lo), static tail after
    int dynv4 = nv4 - TAIL_V4;
    if (dynv4 < 0) dynv4 = 0;
    const int nchunks = dynv4 / WCHUNK_V4;
    const int tail_lo = nchunks * WCHUNK_V4;

    // ------------------- phase 1: min/max -------------------
    float vmin = 3.402823466e38f;
    float vmax = -3.402823466e38f;

    // (a) DYNAMIC warp chunks over streaming region (.cs, no block syncs)
    {
        int cur;
        if (lane == 0) cur = (int)atomicAdd(&g_ctr1[slot], 1u);
        cur = __shfl_sync(0xFFFFFFFFu, cur, 0);
        while (cur < nchunks) {
            int nxt = 0;
            if (lane == 0) nxt = (int)atomicAdd(&g_ctr1[slot], 1u);  // prefetch claim
            const int base = cur * WCHUNK_V4 + lane;
            #pragma unroll 4
            for (int u = 0; u < WCHUNK_ITERS; u++) {
                float4 v = __ldcs(&x4[base + u * 32]);
                vmin = fminf(vmin, fminf(fminf(v.x, v.y), fminf(v.z, v.w)));
                vmax = fmaxf(vmax, fmaxf(fmaxf(v.x, v.y), fmaxf(v.z, v.w)));
            }
            cur = __shfl_sync(0xFFFFFFFFu, nxt, 0);
        }
    }
    // (b) STATIC tail last: default loads -> freshest lines in L2 at barrier
    {
        int i = tid0;
        if (tail_lo > tid0)
            i = tid0 + ((tail_lo - tid0 + stride - 1) / stride) * stride;
        #pragma unroll 4
        for (; i < nv4; i += stride) {
            float4 v = x4[i];
            vmin = fminf(vmin, fminf(fminf(v.x, v.y), fminf(v.z, v.w)));
            vmax = fmaxf(vmax, fmaxf(fmaxf(v.x, v.y), fmaxf(v.z, v.w)));
        }
    }
    if (blockIdx.x == 0 && threadIdx.x < (n & 3)) {  // scalar tail (defensive)
        float v = xs[(nv4 << 2) + threadIdx.x];
        vmin = fminf(vmin, v);
        vmax = fmaxf(vmax, v);
    }

    #pragma unroll
    for (int o = 16; o; o >>= 1) {
        vmin = fminf(vmin, __shfl_xor_sync(0xFFFFFFFFu, vmin, o));
        vmax = fmaxf(vmax, __shfl_xor_sync(0xFFFFFFFFu, vmax, o));
    }
    if (lane == 0) { smin[wid] = vmin; smax[wid] = vmax; }
    __syncthreads();

    // ------------------- barrier with folded reduction -------------------
    if (threadIdx.x == 0) {
        float bmin = smin[0], bmax = smax[0];
        #pragma unroll
        for (int w = 1; w < 8; w++) {
            bmin = fminf(bmin, smin[w]);
            bmax = fmaxf(bmax, smax[w]);
        }
        atomicMin(&g_mm[slot][0], flipf(bmin));
        atomicMax(&g_mm[slot][1], flipf(bmax));
        __threadfence();
        unsigned int old = atomicAdd(&g_count, 1u);
        if (old == NPART - 1) {
            // last arrival: finalize, publish, reset alternate-slot state
            float fmin = unflipf(ld_acq(&g_mm[slot][0]));
            float fmax = unflipf(ld_acq(&g_mm[slot][1]));
            float S = 31.0f / (fmax - fmin + 1e-6f);
            g_sb[slot] = make_float2(S, -fmin * S);
            g_mm[slot ^ 1][0] = 0xFFFFFFFFu;         // next replay's slot
            g_mm[slot ^ 1][1] = 0u;
            g_ctr1[slot ^ 1] = 0u;
            g_ctr2[slot ^ 1] = 0u;
            atomicExch(&g_count, 0u);
            __threadfence();
            atomicAdd(&g_release, 1u);
            s_SB[0] = S;
            s_SB[1] = -fmin * S;
        } else {
            while (ld_acq(&g_release) == epoch0) __nanosleep(16);
            float2 sb = g_sb[slot];                  // ordered after acquire
            s_SB[0] = sb.x;
            s_SB[1] = sb.y;
        }
    }
    __syncthreads();
    const float S = s_SB[0];
    const float B = s_SB[1];

    // ------------------- phase 2: transform -------------------
    float4* __restrict__ o4 = (float4*)outs;

    // (a) STATIC tail FIRST for all blocks: own indices reversed -> L2 hits
    if (tid0 < nv4) {
        const int jlast = tid0 + ((nv4 - 1 - tid0) / stride) * stride;
        #pragma unroll 2
        for (int j = jlast; j >= tail_lo; j -= stride) {
            float4 v = __ldcs(&x4[j]);
            float4 r;
            r.x = auf_eval(v.x, S, B, tab);
            r.y = auf_eval(v.y, S, B, tab);
            r.z = auf_eval(v.z, S, B, tab);
            r.w = auf_eval(v.w, S, B, tab);
            __stcs(&o4[j], r);
        }
    }
    // (b) DYNAMIC warp chunks over streaming region (no block syncs)
    {
        int cur;
        if (lane == 0) cur = (int)atomicAdd(&g_ctr2[slot], 1u);
        cur = __shfl_sync(0xFFFFFFFFu, cur, 0);
        while (cur < nchunks) {
            int nxt = 0;
            if (lane == 0) nxt = (int)atomicAdd(&g_ctr2[slot], 1u);  // prefetch claim
            const int base = cur * WCHUNK_V4 + lane;
            #pragma unroll 4
            for (int u = 0; u < WCHUNK_ITERS; u++) {
                const int j = base + u * 32;
                float4 v = __ldcs(&x4[j]);
                float4 r;
                r.x = auf_eval(v.x, S, B, tab);
                r.y = auf_eval(v.y, S, B, tab);
                r.z = auf_eval(v.z, S, B, tab);
                r.w = auf_eval(v.w, S, B, tab);
                __stcs(&o4[j], r);
            }
            cur = __shfl_sync(0xFFFFFFFFu, nxt, 0);
        }
    }
    if (blockIdx.x == 0 && threadIdx.x < (n & 3)) {  // scalar tail
        const int e = (nv4 << 2) + threadIdx.x;
        outs[e] = auf_eval(xs[e], S, B, tab);
    }
}

// ---------------------------------------------------------------------------
// Launch: ONE kernel. No sync, no allocation -> graph-capturable.
// ---------------------------------------------------------------------------
extern "C" void kernel_launch(void* const* d_in, const int* in_sizes, int n_in,
                              void* d_out, int out_size) {
    const float* x  = (const float*)d_in[0];   // (64, 1048576) fp32
    const float* cp = (const float*)d_in[1];   // (32,) control points
    // d_in[2] = knots: uniform linspace(0,1,32) -> analytic, unused
    const int n = in_sizes[0];

    auf_fused_kernel<<<NPART, NTHREADS>>>(x, cp, (float*)d_out, n);
}

// round 16
// speedup vs baseline: 1.2866x; 1.2866x over previous
#include <cuda_runtime.h>

// ---------------------------------------------------------------------------
// AdaptiveUnivariateFunction — fused persistent kernel (round 16).
//   xn = (x - min)/(max - min + 1e-6) in [0,1)
//   out = cp[idx] + t*(cp[idx+1]-cp[idx]),  idx=clamp(floor(xn*31),0,30)
//
// R14 config with 16KB dynamic chunks (was 32KB): one chunk = ~3.3us of
// block time, and dynamic claiming balances only to within ~1 chunk, so
// smaller chunks halve the straggler skew at the grid barrier and at
// kernel end. (R15's warp-claiming is dead: it destroyed block-level load
// batching, -27% bandwidth.)
//
// Validated knobs: block claims double-buffered (race-free), tail 96MB
// natural LRU, tail-first phase 2, .cs loads/stores, tail unroll 2,
// ping-pong barrier state (no init kernel, graph-replay safe).
// ---------------------------------------------------------------------------

#define NPART 1184               // 148 SMs x 8 blocks -> exactly one wave
#define NTHREADS 256
#define CHUNK_ITERS 4            // iterations per claimed chunk
#define CHUNK_V4 (CHUNK_ITERS * NTHREADS)   // 1024 float4 = 16 KB
#define TAIL_V4 6291456          // 96 MB / 16 B static tail (L2-fresh)

// ping-pong state; slot = epoch & 1
__device__ unsigned int g_mm[2][2] = {{0xFFFFFFFFu, 0u}, {0xFFFFFFFFu, 0u}};
__device__ float2 g_sb[2];                 // published (S, B)
__device__ unsigned int g_ctr1[2];         // phase-1 chunk counter
__device__ unsigned int g_ctr2[2];         // phase-2 chunk counter
__device__ unsigned int g_count;           // barrier arrivals
__device__ unsigned int g_release;         // barrier epoch (monotone)

__device__ __forceinline__ unsigned int ld_acq(const unsigned int* p) {
    unsigned int v;
    asm volatile("ld.global.acquire.gpu.u32 %0, [%1];" : "=r"(v) : "l"(p));
    return v;
}
__device__ __forceinline__ unsigned int flipf(float f) {
    unsigned int u = __float_as_uint(f);
    return u ^ ((unsigned int)(-(int)(u >> 31)) | 0x80000000u);
}
__device__ __forceinline__ float unflipf(unsigned int u) {
    return __uint_as_float(u ^ (((u >> 31) - 1u) | 0x80000000u));
}

__device__ __forceinline__ float auf_eval(float x, float S, float B,
                                          const float2* __restrict__ tab) {
    float xn31 = fmaf(x, S, B);            // xn * 31
    int idx = (int)xn31;                   // trunc == floor here
    idx = max(0, min(idx, 30));            // boundary rounding value-neutral
    float2 ad = tab[idx];                  // (cp[idx], cp[idx+1]-cp[idx])
    return fmaf(xn31 - (float)idx, ad.y, ad.x);
}

__global__ void __launch_bounds__(NTHREADS, 8)
auf_fused_kernel(const float* __restrict__ xs,
                 const float* __restrict__ cp,
                 float* __restrict__ outs,
                 int n) {
    __shared__ float2 tab[32];
    __shared__ float smin[8], smax[8];
    __shared__ float s_SB[2];
    __shared__ int s_next[2];              // double-buffered chunk claims

    // epoch/slot: only thread 0 uses them (atomics + claims)
    unsigned int epoch0 = 0;
    int slot = 0;
    if (threadIdx.x == 0) {
        epoch0 = ld_acq(&g_release);
        slot = (int)(epoch0 & 1u);
    }

    // spline table: (cp[i], cp[i+1]-cp[i]); slot 31 duplicates 30
    if (threadIdx.x < 32) {
        int i = (threadIdx.x < 31) ? (int)threadIdx.x : 30;
        float c0 = cp[i];
        float c1 = cp[i + 1];
        tab[threadIdx.x] = make_float2(c0, c1 - c0);
    }

    const float4* __restrict__ x4 = (const float4*)xs;
    const int nv4 = n >> 2;
    const int tid0 = blockIdx.x * NTHREADS + (int)threadIdx.x;
    const int stride = NPART * NTHREADS;

    // region split: dynamic chunks over [0, tail_lo), static tail [tail_lo, nv4)
    int dynv4 = nv4 - TAIL_V4;
    if (dynv4 < 0) dynv4 = 0;
    const int nchunks = dynv4 / CHUNK_V4;
    const int tail_lo = nchunks * CHUNK_V4;

    // ------------------- phase 1: min/max -------------------
    float vmin = 3.402823466e38f;
    float vmax = -3.402823466e38f;

    // (a) DYNAMIC chunks over streaming region (.cs; double-buffered claims)
    if (threadIdx.x == 0) s_next[0] = (int)atomicAdd(&g_ctr1[slot], 1u);
    __syncthreads();
    {
        int buf = 0;
        int cur = s_next[0];
        while (cur < nchunks) {
            if (threadIdx.x == 0)                    // claim into OTHER slot
                s_next[buf ^ 1] = (int)atomicAdd(&g_ctr1[slot], 1u);
            const int base = cur * CHUNK_V4 + (int)threadIdx.x;
            #pragma unroll
            for (int u = 0; u < CHUNK_ITERS; u++) {
                float4 v = __ldcs(&x4[base + u * NTHREADS]);
                vmin = fminf(vmin, fminf(fminf(v.x, v.y), fminf(v.z, v.w)));
                vmax = fmaxf(vmax, fmaxf(fmaxf(v.x, v.y), fmaxf(v.z, v.w)));
            }
            __syncthreads();                         // orders claim write -> read
            buf ^= 1;
            cur = s_next[buf];
        }
    }
    // (b) STATIC tail last: default loads -> freshest lines in L2 at barrier
    {
        int i = tid0;
        if (tail_lo > tid0)
            i = tid0 + ((tail_lo - tid0 + stride - 1) / stride) * stride;
        #pragma unroll 4
        for (; i < nv4; i += stride) {
            float4 v = x4[i];
            vmin = fminf(vmin, fminf(fminf(v.x, v.y), fminf(v.z, v.w)));
            vmax = fmaxf(vmax, fmaxf(fmaxf(v.x, v.y), fmaxf(v.z, v.w)));
        }
    }
    if (blockIdx.x == 0 && threadIdx.x < (n & 3)) {  // scalar tail (defensive)
        float v = xs[(nv4 << 2) + threadIdx.x];
        vmin = fminf(vmin, v);
        vmax = fmaxf(vmax, v);
    }

    #pragma unroll
    for (int o = 16; o; o >>= 1) {
        vmin = fminf(vmin, __shfl_xor_sync(0xFFFFFFFFu, vmin, o));
        vmax = fmaxf(vmax, __shfl_xor_sync(0xFFFFFFFFu, vmax, o));
    }
    const int wid = threadIdx.x >> 5;
    if ((threadIdx.x & 31) == 0) { smin[wid] = vmin; smax[wid] = vmax; }
    __syncthreads();

    // ------------------- barrier with folded reduction -------------------
    if (threadIdx.x == 0) {
        float bmin = smin[0], bmax = smax[0];
        #pragma unroll
        for (int w = 1; w < 8; w++) {
            bmin = fminf(bmin, smin[w]);
            bmax = fmaxf(bmax, smax[w]);
        }
        atomicMin(&g_mm[slot][0], flipf(bmin));
        atomicMax(&g_mm[slot][1], flipf(bmax));
        __threadfence();
        unsigned int old = atomicAdd(&g_count, 1u);
        if (old == NPART - 1) {
            // last arrival: finalize, publish, reset alternate-slot state
            float fmin = unflipf(ld_acq(&g_mm[slot][0]));
            float fmax = unflipf(ld_acq(&g_mm[slot][1]));
            float S = 31.0f / (fmax - fmin + 1e-6f);
            g_sb[slot] = make_float2(S, -fmin * S);
            g_mm[slot ^ 1][0] = 0xFFFFFFFFu;         // next replay's slot
            g_mm[slot ^ 1][1] = 0u;
            g_ctr1[slot ^ 1] = 0u;
            g_ctr2[slot ^ 1] = 0u;
            atomicExch(&g_count, 0u);
            __threadfence();
            atomicAdd(&g_release, 1u);
            s_SB[0] = S;
            s_SB[1] = -fmin * S;
        } else {
            while (ld_acq(&g_release) == epoch0) __nanosleep(16);
            float2 sb = g_sb[slot];                  // ordered after acquire
            s_SB[0] = sb.x;
            s_SB[1] = sb.y;
        }
    }
    __syncthreads();
    const float S = s_SB[0];
    const float B = s_SB[1];

    // ------------------- phase 2: transform -------------------
    float4* __restrict__ o4 = (float4*)outs;

    // (a) STATIC tail FIRST for all blocks: own indices reversed -> L2 hits
    if (tid0 < nv4) {
        const int jlast = tid0 + ((nv4 - 1 - tid0) / stride) * stride;
        #pragma unroll 2
        for (int j = jlast; j >= tail_lo; j -= stride) {
            float4 v = __ldcs(&x4[j]);
            float4 r;
            r.x = auf_eval(v.x, S, B, tab);
            r.y = auf_eval(v.y, S, B, tab);
            r.z = auf_eval(v.z, S, B, tab);
            r.w = auf_eval(v.w, S, B, tab);
            __stcs(&o4[j], r);
        }
    }
    // (b) DYNAMIC chunks over streaming region (double-buffered claims)
    if (threadIdx.x == 0) s_next[0] = (int)atomicAdd(&g_ctr2[slot], 1u);
    __syncthreads();
    {
        int buf = 0;
        int cur = s_next[0];
        while (cur < nchunks) {
            if (threadIdx.x == 0)
                s_next[buf ^ 1] = (int)atomicAdd(&g_ctr2[slot], 1u);
            const int base = cur * CHUNK_V4 + (int)threadIdx.x;
            #pragma unroll
            for (int u = 0; u < CHUNK_ITERS; u++) {
                const int j = base + u * NTHREADS;
                float4 v = __ldcs(&x4[j]);
                float4 r;
                r.x = auf_eval(v.x, S, B, tab);
                r.y = auf_eval(v.y, S, B, tab);
                r.z = auf_eval(v.z, S, B, tab);
                r.w = auf_eval(v.w, S, B, tab);
                __stcs(&o4[j], r);
            }
            __syncthreads();
            buf ^= 1;
            cur = s_next[buf];
        }
    }
    if (blockIdx.x == 0 && threadIdx.x < (n & 3)) {  // scalar tail
        const int e = (nv4 << 2) + threadIdx.x;
        outs[e] = auf_eval(xs[e], S, B, tab);
    }
}

// ---------------------------------------------------------------------------
// Launch: ONE kernel. No sync, no allocation -> graph-capturable.
// ---------------------------------------------------------------------------
extern "C" void kernel_launch(void* const* d_in, const int* in_sizes, int n_in,
                              void* d_out, int out_size) {
    const float* x  = (const float*)d_in[0];   // (64, 1048576) fp32
    const float* cp = (const float*)d_in[1];   // (32,) control points
    // d_in[2] = knots: uniform linspace(0,1,32) -> analytic, unused
    const int n = in_sizes[0];

    auf_fused_kernel<<<NPART, NTHREADS>>>(x, cp, (float*)d_out, n);
}